// round 2
// baseline (speedup 1.0000x reference)
#include <cuda_runtime.h>
#include <math.h>
#include <stdint.h>

// Problem constants
#define Bq 4
#define Sq 2048
#define Dm 1024
#define Hn 16
#define DHe 64
#define Mrows (Bq*Sq)   // 8192

// Scratch (allocation-free rule: __device__ globals)
__device__ float g_Q[(size_t)Mrows * Dm];
__device__ float g_K[(size_t)Mrows * Dm];
__device__ float g_V[(size_t)Mrows * Dm];
__device__ float g_ctx[(size_t)Mrows * Dm];

// ---------------------------------------------------------------------------
// Tiled fp32 GEMM: C[M,N] = A[M,K] @ W[K,N], M=8192, N=K=1024 (all /128,/16)
// BM=128, BN=128, BK=16, 256 threads, 8x8 per thread (split quadrants).
// SPLIT: scatter store into [B,H,S,DH] layout for Q/K/V.
// ---------------------------------------------------------------------------
constexpr int BM = 128, BN = 128, BK = 16;

template <bool SPLIT>
__global__ __launch_bounds__(256, 2)
void gemm_kernel(const float* __restrict__ A, const float* __restrict__ W,
                 float* __restrict__ C)
{
    __shared__ float As[BK][BM + 4];  // +4 pad keeps 16B alignment, eases store conflicts
    __shared__ float Bs[BK][BN];

    const int tid = threadIdx.x;
    const int m0 = blockIdx.y * BM;
    const int n0 = blockIdx.x * BN;
    const int tx = tid & 15;
    const int ty = tid >> 4;

    // global-load index helpers
    const int ar = tid >> 2;          // 0..63 (A tile row, +64 for second half)
    const int ak = (tid & 3) << 2;    // k offset {0,4,8,12}
    const int br = tid >> 5;          // 0..7  (B tile k-row, +8 for second half)
    const int bc = (tid & 31) << 2;   // col offset

    float acc[8][8];
#pragma unroll
    for (int i = 0; i < 8; i++)
#pragma unroll
        for (int j = 0; j < 8; j++) acc[i][j] = 0.f;

    for (int k0 = 0; k0 < Dm; k0 += BK) {
#pragma unroll
        for (int hh = 0; hh < 2; hh++) {
            const int row = ar + hh * 64;
            float4 av = *(const float4*)(A + (size_t)(m0 + row) * Dm + k0 + ak);
            As[ak + 0][row] = av.x;
            As[ak + 1][row] = av.y;
            As[ak + 2][row] = av.z;
            As[ak + 3][row] = av.w;
        }
#pragma unroll
        for (int hh = 0; hh < 2; hh++) {
            const int krow = br + hh * 8;
            *(float4*)&Bs[krow][bc] =
                *(const float4*)(W + (size_t)(k0 + krow) * Dm + n0 + bc);
        }
        __syncthreads();

#pragma unroll
        for (int k = 0; k < BK; k++) {
            float a[8], b[8];
            *(float4*)&a[0] = *(float4*)&As[k][ty * 4];
            *(float4*)&a[4] = *(float4*)&As[k][64 + ty * 4];
            *(float4*)&b[0] = *(float4*)&Bs[k][tx * 4];
            *(float4*)&b[4] = *(float4*)&Bs[k][64 + tx * 4];
#pragma unroll
            for (int i = 0; i < 8; i++)
#pragma unroll
                for (int j = 0; j < 8; j++)
                    acc[i][j] = fmaf(a[i], b[j], acc[i][j]);
        }
        __syncthreads();
    }

#pragma unroll
    for (int ih = 0; ih < 2; ih++)
#pragma unroll
        for (int ii = 0; ii < 4; ii++) {
            const int m = m0 + ih * 64 + ty * 4 + ii;
#pragma unroll
            for (int jh = 0; jh < 2; jh++) {
                const int n = n0 + jh * 64 + tx * 4;
                float4 v = make_float4(acc[ih * 4 + ii][jh * 4 + 0],
                                       acc[ih * 4 + ii][jh * 4 + 1],
                                       acc[ih * 4 + ii][jh * 4 + 2],
                                       acc[ih * 4 + ii][jh * 4 + 3]);
                if (SPLIT) {
                    // m = b*S + s ; n = h*64 + dh (4-chunk never crosses head)
                    const int bb = m >> 11;
                    const int ss = m & (Sq - 1);
                    const int hh2 = n >> 6;
                    const int dh = n & 63;
                    *(float4*)(C + ((size_t)((bb * Hn + hh2) * Sq + ss)) * DHe + dh) = v;
                } else {
                    *(float4*)(C + (size_t)m * Dm + n) = v;
                }
            }
        }
}

// ---------------------------------------------------------------------------
// Causal flash attention, fp32.
// Q/K/V in [B,H,S,DH]. One block = 64 query rows of one (b,h).
// 256 threads: 4 threads per query row. KV tiles of 32 keys.
// Online softmax; P broadcast to PV via warp shuffle (no P smem).
// ctx written in [B,S,D] layout.
// ---------------------------------------------------------------------------
__global__ __launch_bounds__(256, 4)
void attn_kernel(const float* __restrict__ Q, const float* __restrict__ K,
                 const float* __restrict__ V, float* __restrict__ ctx)
{
    __shared__ float Qs[64][68];
    __shared__ float Ks[32][68];
    __shared__ float Vs[32][68];

    const int tid = threadIdx.x;
    const int qt = blockIdx.x;        // q tile 0..31
    const int bh = blockIdx.y;        // 0..63
    const int b = bh >> 4;
    const int h = bh & 15;

    const float* Qb = Q + (size_t)bh * Sq * DHe;
    const float* Kb = K + (size_t)bh * Sq * DHe;
    const float* Vb = V + (size_t)bh * Sq * DHe;

    const int r = tid >> 2;           // query row within tile, 0..63
    const int c = tid & 3;            // quarter of the row
    const int lane = tid & 31;
    const int gbase = lane & ~3;      // shuffle group base lane

    // Load Q tile (64 x 64), 4 float4 per thread
#pragma unroll
    for (int i = 0; i < 4; i++) {
        const int p = tid + i * 256;
        const int rr = p >> 4;
        const int d4 = (p & 15) * 4;
        *(float4*)&Qs[rr][d4] =
            *(const float4*)&Qb[((size_t)qt * 64 + rr) * DHe + d4];
    }

    float m_run = -INFINITY;
    float l_run = 0.f;
    float acc[16];                    // d = c*4 + 16*qq + e
#pragma unroll
    for (int e = 0; e < 16; e++) acc[e] = 0.f;

    const int iglob = qt * 64 + r;
    const int ntiles = 2 * qt + 2;    // keys 0 .. qt*64+63 in 32-wide tiles

    for (int kt = 0; kt < ntiles; kt++) {
        const int kv0 = kt * 32;
        __syncthreads();              // protect Ks/Vs from previous readers (also fences Qs writes on kt=0)
#pragma unroll
        for (int i = 0; i < 2; i++) {
            const int p = tid + i * 256;
            const int nn = p >> 4;
            const int d4 = (p & 15) * 4;
            *(float4*)&Ks[nn][d4] = *(const float4*)&Kb[(size_t)(kv0 + nn) * DHe + d4];
            *(float4*)&Vs[nn][d4] = *(const float4*)&Vb[(size_t)(kv0 + nn) * DHe + d4];
        }
        __syncthreads();

        // scores: this thread owns n = c + 4*np, np = 0..7
        float s[8];
#pragma unroll
        for (int np = 0; np < 8; np++) s[np] = 0.f;
#pragma unroll
        for (int d4 = 0; d4 < 64; d4 += 4) {
            const float4 q4 = *(float4*)&Qs[r][d4];
#pragma unroll
            for (int np = 0; np < 8; np++) {
                const float4 k4 = *(float4*)&Ks[c + 4 * np][d4];
                s[np] = fmaf(q4.x, k4.x, s[np]);
                s[np] = fmaf(q4.y, k4.y, s[np]);
                s[np] = fmaf(q4.z, k4.z, s[np]);
                s[np] = fmaf(q4.w, k4.w, s[np]);
            }
        }

        float tmax = -INFINITY;
#pragma unroll
        for (int np = 0; np < 8; np++) {
            const int j = kv0 + c + 4 * np;
            s[np] = (j <= iglob) ? s[np] * 0.125f : -INFINITY;  // 1/sqrt(64)
            tmax = fmaxf(tmax, s[np]);
        }
        tmax = fmaxf(tmax, __shfl_xor_sync(0xffffffffu, tmax, 1));
        tmax = fmaxf(tmax, __shfl_xor_sync(0xffffffffu, tmax, 2));

        const float m_new = fmaxf(m_run, tmax);
        const float alpha = __expf(m_run - m_new);  // m_run=-inf first tile -> 0

        float p8[8];
        float psum = 0.f;
#pragma unroll
        for (int np = 0; np < 8; np++) {
            p8[np] = __expf(s[np] - m_new);         // masked -> exp(-inf)=0
            psum += p8[np];
        }
        psum += __shfl_xor_sync(0xffffffffu, psum, 1);
        psum += __shfl_xor_sync(0xffffffffu, psum, 2);

        l_run = l_run * alpha + psum;
        m_run = m_new;
#pragma unroll
        for (int e = 0; e < 16; e++) acc[e] *= alpha;

        // PV: acc[d-slice] += sum_n p[n] * V[n][d]
#pragma unroll
        for (int np = 0; np < 8; np++) {
#pragma unroll
            for (int cc = 0; cc < 4; cc++) {
                const float pbc = __shfl_sync(0xffffffffu, p8[np], gbase + cc);
                const int n = cc + 4 * np;
#pragma unroll
                for (int qq = 0; qq < 4; qq++) {
                    const float4 v4 = *(float4*)&Vs[n][c * 4 + 16 * qq];
                    acc[qq * 4 + 0] = fmaf(pbc, v4.x, acc[qq * 4 + 0]);
                    acc[qq * 4 + 1] = fmaf(pbc, v4.y, acc[qq * 4 + 1]);
                    acc[qq * 4 + 2] = fmaf(pbc, v4.z, acc[qq * 4 + 2]);
                    acc[qq * 4 + 3] = fmaf(pbc, v4.w, acc[qq * 4 + 3]);
                }
            }
        }
    }

    const float inv = 1.f / l_run;
    const int sg = qt * 64 + r;
    float* out = ctx + ((size_t)(b * Sq + sg)) * Dm + h * DHe;
#pragma unroll
    for (int qq = 0; qq < 4; qq++) {
        float4 o = make_float4(acc[qq * 4 + 0] * inv, acc[qq * 4 + 1] * inv,
                               acc[qq * 4 + 2] * inv, acc[qq * 4 + 3] * inv);
        *(float4*)&out[c * 4 + 16 * qq] = o;
    }
}

// ---------------------------------------------------------------------------
extern "C" void kernel_launch(void* const* d_in, const int* in_sizes, int n_in,
                              void* d_out, int out_size)
{
    const float* x  = (const float*)d_in[0];
    const float* Wq = (const float*)d_in[1];
    const float* Wk = (const float*)d_in[2];
    const float* Wv = (const float*)d_in[3];
    const float* Wo = (const float*)d_in[4];
    float* out = (float*)d_out;

    float *pQ, *pK, *pV, *pC;
    cudaGetSymbolAddress((void**)&pQ, g_Q);
    cudaGetSymbolAddress((void**)&pK, g_K);
    cudaGetSymbolAddress((void**)&pV, g_V);
    cudaGetSymbolAddress((void**)&pC, g_ctx);

    const dim3 gg(Dm / BN, Mrows / BM);   // (8, 64)

    gemm_kernel<true><<<gg, 256>>>(x, Wq, pQ);
    gemm_kernel<true><<<gg, 256>>>(x, Wk, pK);
    gemm_kernel<true><<<gg, 256>>>(x, Wv, pV);

    attn_kernel<<<dim3(Sq / 64, Bq * Hn), 256>>>(pQ, pK, pV, pC);

    gemm_kernel<false><<<gg, 256>>>(pC, Wo, out);
}

// round 5
// speedup vs baseline: 1.2585x; 1.2585x over previous
#include <cuda_runtime.h>
#include <cuda_bf16.h>
#include <math.h>
#include <stdint.h>

// Problem constants
#define Bq 4
#define Sq 2048
#define Dm 1024
#define Hn 16
#define DHe 64
#define Mrows (Bq*Sq)   // 8192

// ---------------- scratch (__device__ globals; no allocs allowed) ----------
__device__ float g_Q[(size_t)Mrows * Dm];
__device__ float g_K[(size_t)Mrows * Dm];
__device__ float g_V[(size_t)Mrows * Dm];
__device__ float g_ctx[(size_t)Mrows * Dm];
__device__ __nv_bfloat16 g_xh[(size_t)Mrows * Dm];
__device__ __nv_bfloat16 g_xl[(size_t)Mrows * Dm];
__device__ __nv_bfloat16 g_ch[(size_t)Mrows * Dm];
__device__ __nv_bfloat16 g_cl[(size_t)Mrows * Dm];
__device__ __nv_bfloat16 g_wh[(size_t)4 * Dm * Dm];   // W^T hi, [n][k]
__device__ __nv_bfloat16 g_wl[(size_t)4 * Dm * Dm];   // W^T lo

// ---------------- helpers ---------------------------------------------------
__device__ __forceinline__ uint32_t smem_u32(const void* p) {
    uint32_t a;
    asm("{ .reg .u64 t; cvta.to.shared.u64 t, %1; cvt.u32.u64 %0, t; }"
        : "=r"(a) : "l"(p));
    return a;
}
__device__ __forceinline__ void ldsm4(uint32_t* r, uint32_t a) {
    asm volatile("ldmatrix.sync.aligned.m8n8.x4.shared.b16 {%0,%1,%2,%3}, [%4];"
                 : "=r"(r[0]), "=r"(r[1]), "=r"(r[2]), "=r"(r[3]) : "r"(a));
}
__device__ __forceinline__ void mma16816(float* d, const uint32_t* a,
                                         uint32_t b0, uint32_t b1) {
    asm volatile(
        "mma.sync.aligned.m16n8k16.row.col.f32.bf16.bf16.f32 "
        "{%0,%1,%2,%3},{%4,%5,%6,%7},{%8,%9},{%0,%1,%2,%3};"
        : "+f"(d[0]), "+f"(d[1]), "+f"(d[2]), "+f"(d[3])
        : "r"(a[0]), "r"(a[1]), "r"(a[2]), "r"(a[3]), "r"(b0), "r"(b1));
}
#define CP_ASYNC16(dst, src) \
    asm volatile("cp.async.cg.shared.global [%0], [%1], 16;" :: "r"(dst), "l"(src) : "memory")
#define CP_COMMIT() asm volatile("cp.async.commit_group;" ::: "memory")
#define CP_WAIT(N)  asm volatile("cp.async.wait_group %0;" :: "n"(N) : "memory")

// ---------------- split kernels --------------------------------------------
__global__ void fsplit_kernel(const float* __restrict__ X,
                              __nv_bfloat16* __restrict__ H,
                              __nv_bfloat16* __restrict__ L, int n4)
{
    for (int i = blockIdx.x * blockDim.x + threadIdx.x; i < n4;
         i += gridDim.x * blockDim.x) {
        float4 v = ((const float4*)X)[i];
        __nv_bfloat16 h0 = __float2bfloat16(v.x);
        __nv_bfloat16 h1 = __float2bfloat16(v.y);
        __nv_bfloat16 h2 = __float2bfloat16(v.z);
        __nv_bfloat16 h3 = __float2bfloat16(v.w);
        __nv_bfloat16 l0 = __float2bfloat16(v.x - __bfloat162float(h0));
        __nv_bfloat16 l1 = __float2bfloat16(v.y - __bfloat162float(h1));
        __nv_bfloat16 l2 = __float2bfloat16(v.z - __bfloat162float(h2));
        __nv_bfloat16 l3 = __float2bfloat16(v.w - __bfloat162float(h3));
        __nv_bfloat16 hp[4] = {h0, h1, h2, h3};
        __nv_bfloat16 lp[4] = {l0, l1, l2, l3};
        ((uint2*)H)[i] = *(uint2*)hp;
        ((uint2*)L)[i] = *(uint2*)lp;
    }
}

__global__ void wsplit_kernel(const float* __restrict__ W,
                              __nv_bfloat16* __restrict__ Th,
                              __nv_bfloat16* __restrict__ Tl)
{
    __shared__ float t[32][33];
    const int bx = blockIdx.x * 32;
    const int by = blockIdx.y * 32;
    const int row = threadIdx.x >> 5;
    const int col = threadIdx.x & 31;
#pragma unroll
    for (int p = 0; p < 4; p++)
        t[row + 8 * p][col] = W[(size_t)(by + row + 8 * p) * Dm + bx + col];
    __syncthreads();
#pragma unroll
    for (int p = 0; p < 4; p++) {
        const int n = bx + row + 8 * p;
        const int k = by + col;
        float v = t[col][row + 8 * p];
        __nv_bfloat16 h = __float2bfloat16(v);
        __nv_bfloat16 l = __float2bfloat16(v - __bfloat162float(h));
        Th[(size_t)n * Dm + k] = h;
        Tl[(size_t)n * Dm + k] = l;
    }
}

// ---------------- HMMA GEMM -------------------------------------------------
// C[M,N] = A @ B^T. A split (Ah,Al) [M,K] bf16, B^T split (Bh,Bl) [N,K] bf16.
// Block 128x128, BK=32, 8 warps of 64x32, mma.m16n8k16, 2-stage cp.async.
constexpr int APAD    = 40;                    // row stride in bf16 (80B)
constexpr int TILE_B  = 128 * APAD * 2;        // 10240
constexpr int STAGE_B = 4 * TILE_B;            // 40960
constexpr int SMEM_GEMM = 2 * STAGE_B;         // 81920
constexpr int NST = Dm / 32;                   // 32 k-stages

__device__ __forceinline__ void g_load_stage(
    int s, int tid, uint32_t sb,
    const __nv_bfloat16* Ah, const __nv_bfloat16* Al,
    const __nv_bfloat16* Bh, const __nv_bfloat16* Bl, int m0, int n0)
{
    const int k0 = s * 32;
    const uint32_t base = sb + (s & 1) * STAGE_B;
#pragma unroll
    for (int i = 0; i < 8; i++) {
        const int id = tid + i * 256;
        const int tile = id >> 9;          // 0:Ah 1:Al 2:Bh 3:Bl
        const int idx = id & 511;
        const int row = idx >> 2;
        const int ch  = idx & 3;
        const int gk  = k0 + ch * 8;
        const __nv_bfloat16* src;
        if (tile == 0)      src = Ah + (size_t)(m0 + row) * Dm + gk;
        else if (tile == 1) src = Al + (size_t)(m0 + row) * Dm + gk;
        else if (tile == 2) src = Bh + (size_t)(n0 + row) * Dm + gk;
        else                src = Bl + (size_t)(n0 + row) * Dm + gk;
        const uint32_t dst = base + tile * TILE_B + row * (APAD * 2) + ch * 16;
        CP_ASYNC16(dst, src);
    }
    CP_COMMIT();
}

template <bool SPLIT>
__global__ __launch_bounds__(256)
void gemm_hmma(const __nv_bfloat16* __restrict__ Ah, const __nv_bfloat16* __restrict__ Al,
               const __nv_bfloat16* __restrict__ Bh, const __nv_bfloat16* __restrict__ Bl,
               float* __restrict__ C)
{
    extern __shared__ char smem[];
    const uint32_t sb = smem_u32(smem);
    const int tid = threadIdx.x;
    const int wid = tid >> 5;
    const int lane = tid & 31;
    const int warp_m = wid & 1;          // 0..1 -> m offset 64*warp_m
    const int warp_n = wid >> 1;         // 0..3 -> n offset 32*warp_n
    const int m0 = blockIdx.y * 128;
    const int n0 = blockIdx.x * 128;

    // per-lane ldmatrix offsets (bytes, within a tile)
    const int a_r = (lane & 7) + ((lane >> 3) & 1) * 8;
    const int a_c = ((lane >> 4) & 1) * 8;
    const uint32_t a_off = (uint32_t)((warp_m * 64 + a_r) * APAD + a_c) * 2;
    const int b_n = (lane & 7) + ((lane >> 4) & 1) * 8;
    const int b_k = ((lane >> 3) & 1) * 8;
    const uint32_t b_off = (uint32_t)((warp_n * 32 + b_n) * APAD + b_k) * 2;

    float acc[4][4][4];
#pragma unroll
    for (int i = 0; i < 4; i++)
#pragma unroll
        for (int j = 0; j < 4; j++)
#pragma unroll
            for (int e = 0; e < 4; e++) acc[i][j][e] = 0.f;

    g_load_stage(0, tid, sb, Ah, Al, Bh, Bl, m0, n0);
    g_load_stage(1, tid, sb, Ah, Al, Bh, Bl, m0, n0);

    for (int s = 0; s < NST; s++) {
        if (s + 2 < NST) CP_WAIT(1); else CP_WAIT(0);
        __syncthreads();
        const uint32_t base = sb + (s & 1) * STAGE_B;

#pragma unroll
        for (int ks = 0; ks < 2; ks++) {
            const uint32_t kb = ks * 32;   // 16 bf16 = 32B
            uint32_t ah[4][4], al[4][4], bh[2][4], bl[2][4];
#pragma unroll
            for (int mf = 0; mf < 4; mf++) {
                const uint32_t ro = mf * 16 * APAD * 2 + kb;
                ldsm4(ah[mf], base + 0 * TILE_B + a_off + ro);
                ldsm4(al[mf], base + 1 * TILE_B + a_off + ro);
            }
#pragma unroll
            for (int nh = 0; nh < 2; nh++) {
                const uint32_t ro = nh * 16 * APAD * 2 + kb;
                ldsm4(bh[nh], base + 2 * TILE_B + b_off + ro);
                ldsm4(bl[nh], base + 3 * TILE_B + b_off + ro);
            }
#pragma unroll
            for (int mf = 0; mf < 4; mf++) {
#pragma unroll
                for (int nf = 0; nf < 4; nf++) {
                    const int nh = nf >> 1;
                    const int sel = (nf & 1) * 2;
                    const uint32_t bh0 = bh[nh][sel], bh1 = bh[nh][sel + 1];
                    const uint32_t bl0 = bl[nh][sel], bl1 = bl[nh][sel + 1];
                    mma16816(acc[mf][nf], ah[mf], bh0, bh1);
                    mma16816(acc[mf][nf], ah[mf], bl0, bl1);
                    mma16816(acc[mf][nf], al[mf], bh0, bh1);
                }
            }
        }
        __syncthreads();
        if (s + 2 < NST)
            g_load_stage(s + 2, tid, sb, Ah, Al, Bh, Bl, m0, n0);
    }

    // epilogue: d0,d1 -> row g, cols q*2..+1 ; d2,d3 -> row g+8
    const int g = lane >> 2;
    const int q = lane & 3;
#pragma unroll
    for (int mf = 0; mf < 4; mf++) {
#pragma unroll
        for (int nf = 0; nf < 4; nf++) {
#pragma unroll
            for (int hrow = 0; hrow < 2; hrow++) {
                const int m = m0 + warp_m * 64 + mf * 16 + g + hrow * 8;
                const int n = n0 + warp_n * 32 + nf * 8 + q * 2;
                float2 v = make_float2(acc[mf][nf][hrow * 2 + 0],
                                       acc[mf][nf][hrow * 2 + 1]);
                if (SPLIT) {
                    const int bb = m >> 11;
                    const int ss = m & (Sq - 1);
                    const int h2 = n >> 6;
                    const int dh = n & 63;
                    *(float2*)(C + ((size_t)((bb * Hn + h2) * Sq + ss)) * DHe + dh) = v;
                } else {
                    *(float2*)(C + (size_t)m * Dm + n) = v;
                }
            }
        }
    }
}

// ---------------------------------------------------------------------------
// Causal flash attention, fp32 (unchanged).
// ---------------------------------------------------------------------------
__global__ __launch_bounds__(256, 4)
void attn_kernel(const float* __restrict__ Q, const float* __restrict__ K,
                 const float* __restrict__ V, float* __restrict__ ctx)
{
    __shared__ float Qs[64][68];
    __shared__ float Ks[32][68];
    __shared__ float Vs[32][68];

    const int tid = threadIdx.x;
    const int qt = blockIdx.x;
    const int bh = blockIdx.y;
    const int b = bh >> 4;
    const int h = bh & 15;

    const float* Qb = Q + (size_t)bh * Sq * DHe;
    const float* Kb = K + (size_t)bh * Sq * DHe;
    const float* Vb = V + (size_t)bh * Sq * DHe;

    const int r = tid >> 2;
    const int c = tid & 3;
    const int lane = tid & 31;
    const int gbase = lane & ~3;

#pragma unroll
    for (int i = 0; i < 4; i++) {
        const int p = tid + i * 256;
        const int rr = p >> 4;
        const int d4 = (p & 15) * 4;
        *(float4*)&Qs[rr][d4] =
            *(const float4*)&Qb[((size_t)qt * 64 + rr) * DHe + d4];
    }

    float m_run = -INFINITY;
    float l_run = 0.f;
    float acc[16];
#pragma unroll
    for (int e = 0; e < 16; e++) acc[e] = 0.f;

    const int iglob = qt * 64 + r;
    const int ntiles = 2 * qt + 2;

    for (int kt = 0; kt < ntiles; kt++) {
        const int kv0 = kt * 32;
        __syncthreads();
#pragma unroll
        for (int i = 0; i < 2; i++) {
            const int p = tid + i * 256;
            const int nn = p >> 4;
            const int d4 = (p & 15) * 4;
            *(float4*)&Ks[nn][d4] = *(const float4*)&Kb[(size_t)(kv0 + nn) * DHe + d4];
            *(float4*)&Vs[nn][d4] = *(const float4*)&Vb[(size_t)(kv0 + nn) * DHe + d4];
        }
        __syncthreads();

        float s[8];
#pragma unroll
        for (int np = 0; np < 8; np++) s[np] = 0.f;
#pragma unroll
        for (int d4 = 0; d4 < 64; d4 += 4) {
            const float4 q4 = *(float4*)&Qs[r][d4];
#pragma unroll
            for (int np = 0; np < 8; np++) {
                const float4 k4 = *(float4*)&Ks[c + 4 * np][d4];
                s[np] = fmaf(q4.x, k4.x, s[np]);
                s[np] = fmaf(q4.y, k4.y, s[np]);
                s[np] = fmaf(q4.z, k4.z, s[np]);
                s[np] = fmaf(q4.w, k4.w, s[np]);
            }
        }

        float tmax = -INFINITY;
#pragma unroll
        for (int np = 0; np < 8; np++) {
            const int j = kv0 + c + 4 * np;
            s[np] = (j <= iglob) ? s[np] * 0.125f : -INFINITY;
            tmax = fmaxf(tmax, s[np]);
        }
        tmax = fmaxf(tmax, __shfl_xor_sync(0xffffffffu, tmax, 1));
        tmax = fmaxf(tmax, __shfl_xor_sync(0xffffffffu, tmax, 2));

        const float m_new = fmaxf(m_run, tmax);
        const float alpha = __expf(m_run - m_new);

        float p8[8];
        float psum = 0.f;
#pragma unroll
        for (int np = 0; np < 8; np++) {
            p8[np] = __expf(s[np] - m_new);
            psum += p8[np];
        }
        psum += __shfl_xor_sync(0xffffffffu, psum, 1);
        psum += __shfl_xor_sync(0xffffffffu, psum, 2);

        l_run = l_run * alpha + psum;
        m_run = m_new;
#pragma unroll
        for (int e = 0; e < 16; e++) acc[e] *= alpha;

#pragma unroll
        for (int np = 0; np < 8; np++) {
#pragma unroll
            for (int cc = 0; cc < 4; cc++) {
                const float pbc = __shfl_sync(0xffffffffu, p8[np], gbase + cc);
                const int n = cc + 4 * np;
#pragma unroll
                for (int qq = 0; qq < 4; qq++) {
                    const float4 v4 = *(float4*)&Vs[n][c * 4 + 16 * qq];
                    acc[qq * 4 + 0] = fmaf(pbc, v4.x, acc[qq * 4 + 0]);
                    acc[qq * 4 + 1] = fmaf(pbc, v4.y, acc[qq * 4 + 1]);
                    acc[qq * 4 + 2] = fmaf(pbc, v4.z, acc[qq * 4 + 2]);
                    acc[qq * 4 + 3] = fmaf(pbc, v4.w, acc[qq * 4 + 3]);
                }
            }
        }
    }

    const float inv = 1.f / l_run;
    const int sg = qt * 64 + r;
    float* out = ctx + ((size_t)(b * Sq + sg)) * Dm + h * DHe;
#pragma unroll
    for (int qq = 0; qq < 4; qq++) {
        float4 o = make_float4(acc[qq * 4 + 0] * inv, acc[qq * 4 + 1] * inv,
                               acc[qq * 4 + 2] * inv, acc[qq * 4 + 3] * inv);
        *(float4*)&out[c * 4 + 16 * qq] = o;
    }
}

// ---------------------------------------------------------------------------
extern "C" void kernel_launch(void* const* d_in, const int* in_sizes, int n_in,
                              void* d_out, int out_size)
{
    const float* x  = (const float*)d_in[0];
    const float* Wq = (const float*)d_in[1];
    const float* Wk = (const float*)d_in[2];
    const float* Wv = (const float*)d_in[3];
    const float* Wo = (const float*)d_in[4];
    float* out = (float*)d_out;

    float *pQ, *pK, *pV, *pC;
    __nv_bfloat16 *xh, *xl, *ch, *cl, *wh, *wl;
    cudaGetSymbolAddress((void**)&pQ, g_Q);
    cudaGetSymbolAddress((void**)&pK, g_K);
    cudaGetSymbolAddress((void**)&pV, g_V);
    cudaGetSymbolAddress((void**)&pC, g_ctx);
    cudaGetSymbolAddress((void**)&xh, g_xh);
    cudaGetSymbolAddress((void**)&xl, g_xl);
    cudaGetSymbolAddress((void**)&ch, g_ch);
    cudaGetSymbolAddress((void**)&cl, g_cl);
    cudaGetSymbolAddress((void**)&wh, g_wh);
    cudaGetSymbolAddress((void**)&wl, g_wl);

    cudaFuncSetAttribute(gemm_hmma<true>,  cudaFuncAttributeMaxDynamicSharedMemorySize, SMEM_GEMM);
    cudaFuncSetAttribute(gemm_hmma<false>, cudaFuncAttributeMaxDynamicSharedMemorySize, SMEM_GEMM);

    const int n4 = Mrows * Dm / 4;
    const size_t WSZ = (size_t)Dm * Dm;

    fsplit_kernel<<<2048, 256>>>(x, xh, xl, n4);
    {
        dim3 wg(Dm / 32, Dm / 32);
        wsplit_kernel<<<wg, 256>>>(Wq, wh + 0 * WSZ, wl + 0 * WSZ);
        wsplit_kernel<<<wg, 256>>>(Wk, wh + 1 * WSZ, wl + 1 * WSZ);
        wsplit_kernel<<<wg, 256>>>(Wv, wh + 2 * WSZ, wl + 2 * WSZ);
        wsplit_kernel<<<wg, 256>>>(Wo, wh + 3 * WSZ, wl + 3 * WSZ);
    }

    const dim3 gg(Dm / 128, Mrows / 128);   // (8, 64)
    gemm_hmma<true><<<gg, 256, SMEM_GEMM>>>(xh, xl, wh + 0 * WSZ, wl + 0 * WSZ, pQ);
    gemm_hmma<true><<<gg, 256, SMEM_GEMM>>>(xh, xl, wh + 1 * WSZ, wl + 1 * WSZ, pK);
    gemm_hmma<true><<<gg, 256, SMEM_GEMM>>>(xh, xl, wh + 2 * WSZ, wl + 2 * WSZ, pV);

    attn_kernel<<<dim3(Sq / 64, Bq * Hn), 256>>>(pQ, pK, pV, pC);

    fsplit_kernel<<<2048, 256>>>(pC, ch, cl, n4);
    gemm_hmma<false><<<gg, 256, SMEM_GEMM>>>(ch, cl, wh + 3 * WSZ, wl + 3 * WSZ, out);
}

// round 7
// speedup vs baseline: 3.8050x; 3.0234x over previous
#include <cuda_runtime.h>
#include <cuda_bf16.h>
#include <math.h>
#include <stdint.h>

// Problem constants
#define Bq 4
#define Sq 2048
#define Dm 1024
#define Hn 16
#define DHe 64
#define Mrows (Bq*Sq)   // 8192

typedef __nv_bfloat16 bf16;

// ---------------- scratch (__device__ globals; no allocs allowed) ----------
__device__ bf16 g_xh[(size_t)Mrows * Dm];
__device__ bf16 g_xl[(size_t)Mrows * Dm];
__device__ bf16 g_wh[(size_t)4 * Dm * Dm];   // W^T hi, [n][k]
__device__ bf16 g_wl[(size_t)4 * Dm * Dm];   // W^T lo
__device__ bf16 g_qh[(size_t)Mrows * Dm];    // [B,H,S,DH] split pairs
__device__ bf16 g_ql[(size_t)Mrows * Dm];
__device__ bf16 g_kh[(size_t)Mrows * Dm];
__device__ bf16 g_kl[(size_t)Mrows * Dm];
__device__ bf16 g_vh[(size_t)Mrows * Dm];
__device__ bf16 g_vl[(size_t)Mrows * Dm];
__device__ bf16 g_ch[(size_t)Mrows * Dm];    // ctx split, [B,S,D]
__device__ bf16 g_cl[(size_t)Mrows * Dm];

// ---------------- helpers ---------------------------------------------------
__device__ __forceinline__ uint32_t smem_u32(const void* p) {
    uint32_t a;
    asm("{ .reg .u64 t; cvta.to.shared.u64 t, %1; cvt.u32.u64 %0, t; }"
        : "=r"(a) : "l"(p));
    return a;
}
__device__ __forceinline__ void ldsm4(uint32_t* r, uint32_t a) {
    asm volatile("ldmatrix.sync.aligned.m8n8.x4.shared.b16 {%0,%1,%2,%3}, [%4];"
                 : "=r"(r[0]), "=r"(r[1]), "=r"(r[2]), "=r"(r[3]) : "r"(a));
}
__device__ __forceinline__ void ldsm4t(uint32_t* r, uint32_t a) {
    asm volatile("ldmatrix.sync.aligned.m8n8.x4.trans.shared.b16 {%0,%1,%2,%3}, [%4];"
                 : "=r"(r[0]), "=r"(r[1]), "=r"(r[2]), "=r"(r[3]) : "r"(a));
}
__device__ __forceinline__ void mma16816(float* d, const uint32_t* a,
                                         uint32_t b0, uint32_t b1) {
    asm volatile(
        "mma.sync.aligned.m16n8k16.row.col.f32.bf16.bf16.f32 "
        "{%0,%1,%2,%3},{%4,%5,%6,%7},{%8,%9},{%0,%1,%2,%3};"
        : "+f"(d[0]), "+f"(d[1]), "+f"(d[2]), "+f"(d[3])
        : "r"(a[0]), "r"(a[1]), "r"(a[2]), "r"(a[3]), "r"(b0), "r"(b1));
}
#define CP_ASYNC16(dst, src) \
    asm volatile("cp.async.cg.shared.global [%0], [%1], 16;" :: "r"(dst), "l"(src) : "memory")
#define CP_COMMIT() asm volatile("cp.async.commit_group;" ::: "memory")
#define CP_WAIT(N)  asm volatile("cp.async.wait_group %0;" :: "n"(N) : "memory")

// pack two floats -> bf16x2 (lo = a, hi = b)
__device__ __forceinline__ uint32_t packf2(float a, float b) {
    uint32_t r;
    asm("{ .reg .b16 lo, hi; cvt.rn.bf16.f32 lo, %1; cvt.rn.bf16.f32 hi, %2;"
        " mov.b32 %0, {lo, hi}; }" : "=r"(r) : "f"(a), "f"(b));
    return r;
}
// 2-term bf16 split of a float pair
__device__ __forceinline__ void split2(float a, float b, uint32_t& hp, uint32_t& lp) {
    hp = packf2(a, b);
    float fa = __uint_as_float(hp << 16);          // bf16 -> f32 is bits<<16
    float fb = __uint_as_float(hp & 0xffff0000u);
    lp = packf2(a - fa, b - fb);
}

// ---------------- split kernels --------------------------------------------
__global__ void fsplit_kernel(const float* __restrict__ X,
                              bf16* __restrict__ H, bf16* __restrict__ L, int n4)
{
    for (int i = blockIdx.x * blockDim.x + threadIdx.x; i < n4;
         i += gridDim.x * blockDim.x) {
        float4 v = ((const float4*)X)[i];
        uint32_t h01, l01, h23, l23;
        split2(v.x, v.y, h01, l01);
        split2(v.z, v.w, h23, l23);
        ((uint2*)H)[i] = make_uint2(h01, h23);
        ((uint2*)L)[i] = make_uint2(l01, l23);
    }
}

__global__ void wsplit_kernel(const float* __restrict__ W,
                              bf16* __restrict__ Th, bf16* __restrict__ Tl)
{
    __shared__ float t[32][33];
    const int bx = blockIdx.x * 32;
    const int by = blockIdx.y * 32;
    const int row = threadIdx.x >> 5;
    const int col = threadIdx.x & 31;
#pragma unroll
    for (int p = 0; p < 4; p++)
        t[row + 8 * p][col] = W[(size_t)(by + row + 8 * p) * Dm + bx + col];
    __syncthreads();
#pragma unroll
    for (int p = 0; p < 4; p++) {
        const int n = bx + row + 8 * p;
        const int k = by + col;
        float v = t[col][row + 8 * p];
        bf16 h = __float2bfloat16(v);
        bf16 l = __float2bfloat16(v - __bfloat162float(h));
        Th[(size_t)n * Dm + k] = h;
        Tl[(size_t)n * Dm + k] = l;
    }
}

// ---------------- HMMA GEMM -------------------------------------------------
constexpr int APAD    = 40;
constexpr int TILE_B  = 128 * APAD * 2;        // 10240
constexpr int STAGE_B = 4 * TILE_B;            // 40960
constexpr int SMEM_GEMM = 2 * STAGE_B;         // 81920
constexpr int NST = Dm / 32;                   // 32

__device__ __forceinline__ void g_load_stage(
    int s, int tid, uint32_t sb,
    const bf16* Ah, const bf16* Al, const bf16* Bh, const bf16* Bl, int m0, int n0)
{
    const int k0 = s * 32;
    const uint32_t base = sb + (s & 1) * STAGE_B;
#pragma unroll
    for (int i = 0; i < 8; i++) {
        const int id = tid + i * 256;
        const int tile = id >> 9;
        const int idx = id & 511;
        const int row = idx >> 2;
        const int ch  = idx & 3;
        const int gk  = k0 + ch * 8;
        const bf16* src;
        if (tile == 0)      src = Ah + (size_t)(m0 + row) * Dm + gk;
        else if (tile == 1) src = Al + (size_t)(m0 + row) * Dm + gk;
        else if (tile == 2) src = Bh + (size_t)(n0 + row) * Dm + gk;
        else                src = Bl + (size_t)(n0 + row) * Dm + gk;
        const uint32_t dst = base + tile * TILE_B + row * (APAD * 2) + ch * 16;
        CP_ASYNC16(dst, src);
    }
    CP_COMMIT();
}

// SPLIT=1: write bf16 hi/lo pair arrays in [B,H,S,DH]; SPLIT=0: fp32 C [M,N].
template <bool SPLIT>
__global__ __launch_bounds__(256)
void gemm_hmma(const bf16* __restrict__ Ah, const bf16* __restrict__ Al,
               const bf16* __restrict__ Bh, const bf16* __restrict__ Bl,
               float* __restrict__ Cf, bf16* __restrict__ Ch, bf16* __restrict__ Cl)
{
    extern __shared__ char smem[];
    const uint32_t sb = smem_u32(smem);
    const int tid = threadIdx.x;
    const int wid = tid >> 5;
    const int lane = tid & 31;
    const int warp_m = wid & 1;
    const int warp_n = wid >> 1;
    const int m0 = blockIdx.y * 128;
    const int n0 = blockIdx.x * 128;

    const int a_r = (lane & 7) + ((lane >> 3) & 1) * 8;
    const int a_c = ((lane >> 4) & 1) * 8;
    const uint32_t a_off = (uint32_t)((warp_m * 64 + a_r) * APAD + a_c) * 2;
    const int b_n = (lane & 7) + ((lane >> 4) & 1) * 8;
    const int b_k = ((lane >> 3) & 1) * 8;
    const uint32_t b_off = (uint32_t)((warp_n * 32 + b_n) * APAD + b_k) * 2;

    float acc[4][4][4];
#pragma unroll
    for (int i = 0; i < 4; i++)
#pragma unroll
        for (int j = 0; j < 4; j++)
#pragma unroll
            for (int e = 0; e < 4; e++) acc[i][j][e] = 0.f;

    g_load_stage(0, tid, sb, Ah, Al, Bh, Bl, m0, n0);
    g_load_stage(1, tid, sb, Ah, Al, Bh, Bl, m0, n0);

    for (int s = 0; s < NST; s++) {
        if (s + 2 < NST) CP_WAIT(1); else CP_WAIT(0);
        __syncthreads();
        const uint32_t base = sb + (s & 1) * STAGE_B;

#pragma unroll
        for (int ks = 0; ks < 2; ks++) {
            const uint32_t kb = ks * 32;
            uint32_t ah[4][4], al[4][4], bh[2][4], bl[2][4];
#pragma unroll
            for (int mf = 0; mf < 4; mf++) {
                const uint32_t ro = mf * 16 * APAD * 2 + kb;
                ldsm4(ah[mf], base + 0 * TILE_B + a_off + ro);
                ldsm4(al[mf], base + 1 * TILE_B + a_off + ro);
            }
#pragma unroll
            for (int nh = 0; nh < 2; nh++) {
                const uint32_t ro = nh * 16 * APAD * 2 + kb;
                ldsm4(bh[nh], base + 2 * TILE_B + b_off + ro);
                ldsm4(bl[nh], base + 3 * TILE_B + b_off + ro);
            }
#pragma unroll
            for (int mf = 0; mf < 4; mf++) {
#pragma unroll
                for (int nf = 0; nf < 4; nf++) {
                    const int nh = nf >> 1;
                    const int sel = (nf & 1) * 2;
                    const uint32_t bh0 = bh[nh][sel], bh1 = bh[nh][sel + 1];
                    const uint32_t bl0 = bl[nh][sel], bl1 = bl[nh][sel + 1];
                    mma16816(acc[mf][nf], ah[mf], bh0, bh1);
                    mma16816(acc[mf][nf], ah[mf], bl0, bl1);
                    mma16816(acc[mf][nf], al[mf], bh0, bh1);
                }
            }
        }
        __syncthreads();
        if (s + 2 < NST)
            g_load_stage(s + 2, tid, sb, Ah, Al, Bh, Bl, m0, n0);
    }

    const int g = lane >> 2;
    const int q = lane & 3;
#pragma unroll
    for (int mf = 0; mf < 4; mf++) {
#pragma unroll
        for (int nf = 0; nf < 4; nf++) {
#pragma unroll
            for (int hrow = 0; hrow < 2; hrow++) {
                const int m = m0 + warp_m * 64 + mf * 16 + g + hrow * 8;
                const int n = n0 + warp_n * 32 + nf * 8 + q * 2;
                const float v0 = acc[mf][nf][hrow * 2 + 0];
                const float v1 = acc[mf][nf][hrow * 2 + 1];
                if (SPLIT) {
                    const int bb = m >> 11;
                    const int ss = m & (Sq - 1);
                    const int h2 = n >> 6;
                    const int dh = n & 63;
                    const size_t off = ((size_t)((bb * Hn + h2) * Sq + ss)) * DHe + dh;
                    uint32_t hp, lp;
                    split2(v0, v1, hp, lp);
                    *(uint32_t*)(Ch + off) = hp;
                    *(uint32_t*)(Cl + off) = lp;
                } else {
                    *(float2*)(Cf + (size_t)m * Dm + n) = make_float2(v0, v1);
                }
            }
        }
    }
}

// ---------------- tensor-core causal flash attention ------------------------
// 4 warps x 16 q-rows, KV tiles of 64, 3-term bf16 split QK and PV,
// fp32 softmax in registers, ctx written as bf16 hi/lo split [B,S,D].
constexpr int AST  = 72;                 // smem row stride in bf16
constexpr int ASTB = 144;                // bytes
constexpr int Q_BYTES  = 64 * ASTB;      // 9216 per array
constexpr int KV_ARR   = 64 * ASTB;      // 9216
constexpr int STAGE_ATT = 4 * KV_ARR;    // 36864 (Kh,Kl,Vh,Vl)
constexpr int SMEM_ATT  = 2 * Q_BYTES + 2 * STAGE_ATT;  // 92160

__device__ __forceinline__ void att_load_kv(
    uint32_t sb, int st, int tid,
    const bf16* Kh, const bf16* Kl, const bf16* Vh, const bf16* Vl, size_t off)
{
    const uint32_t base = sb + 2 * Q_BYTES + st * STAGE_ATT;
#pragma unroll
    for (int i = 0; i < 16; i++) {
        const int id = tid + i * 128;
        const int arr = id >> 9;
        const int idx = id & 511;
        const int row = idx >> 3;
        const int ch  = idx & 7;
        const bf16* p = (arr == 0) ? Kh : (arr == 1) ? Kl : (arr == 2) ? Vh : Vl;
        CP_ASYNC16(base + arr * KV_ARR + row * ASTB + ch * 16,
                   p + off + (size_t)row * DHe + ch * 8);
    }
    CP_COMMIT();
}

__global__ __launch_bounds__(128)
void attn_tc(const bf16* __restrict__ Qh, const bf16* __restrict__ Ql,
             const bf16* __restrict__ Kh, const bf16* __restrict__ Kl,
             const bf16* __restrict__ Vh, const bf16* __restrict__ Vl,
             bf16* __restrict__ Ch, bf16* __restrict__ Cl)
{
    extern __shared__ char smem[];
    const uint32_t sb = smem_u32(smem);
    const int tid  = threadIdx.x;
    const int w    = tid >> 5;
    const int lane = tid & 31;
    const int qt   = (int)gridDim.x - 1 - (int)blockIdx.x;   // heavy first
    const int bhid = blockIdx.y;
    const int b = bhid >> 4, h = bhid & 15;
    const size_t bhoff = (size_t)bhid * Sq * DHe;

    // ---- load Q tile (hi+lo) ----
#pragma unroll
    for (int i = 0; i < 8; i++) {
        const int id  = tid + i * 128;
        const int arr = id >> 9;             // 0:hi 1:lo
        const int idx = id & 511;
        const int row = idx >> 3, ch = idx & 7;
        const bf16* src = (arr ? Ql : Qh) + bhoff + (size_t)(qt * 64 + row) * DHe + ch * 8;
        CP_ASYNC16(sb + arr * Q_BYTES + row * ASTB + ch * 16, src);
    }
    CP_COMMIT();

    att_load_kv(sb, 0, tid, Kh, Kl, Vh, Vl, bhoff);          // kv tile 0

    CP_WAIT(1);
    __syncthreads();

    // ---- Q fragments to registers ----
    const int a_r = (lane & 7) + ((lane >> 3) & 1) * 8;
    const int a_c = ((lane >> 4) & 1) * 8;
    const uint32_t a_off = (uint32_t)((16 * w + a_r) * ASTB + a_c * 2);
    uint32_t qa_h[4][4], qa_l[4][4];
#pragma unroll
    for (int t = 0; t < 4; t++) {
        ldsm4(qa_h[t], sb + a_off + t * 32);
        ldsm4(qa_l[t], sb + Q_BYTES + a_off + t * 32);
    }

    const int b_n  = (lane & 7) + ((lane >> 4) & 1) * 8;
    const int b_k  = ((lane >> 3) & 1) * 8;
    const int v_kv = ((lane >> 3) & 1) * 8 + (lane & 7);
    const int v_d  = ((lane >> 4) & 1) * 8;
    const int g = lane >> 2;
    const int q = lane & 3;

    float acc_o[8][4];
#pragma unroll
    for (int i = 0; i < 8; i++)
#pragma unroll
        for (int e = 0; e < 4; e++) acc_o[i][e] = 0.f;
    float m0 = -INFINITY, m1 = -INFINITY, l0 = 0.f, l1 = 0.f;

    for (int kt = 0; kt <= qt; kt++) {
        if (kt < qt)
            att_load_kv(sb, (kt + 1) & 1, tid, Kh, Kl, Vh, Vl,
                        bhoff + (size_t)(kt + 1) * 64 * DHe);
        if (kt < qt) CP_WAIT(1); else CP_WAIT(0);
        __syncthreads();
        const uint32_t st = sb + 2 * Q_BYTES + (kt & 1) * STAGE_ATT;

        // ---- scores: S = Q K^T (3-term split) ----
        float sc[8][4];
#pragma unroll
        for (int i = 0; i < 8; i++)
#pragma unroll
            for (int e = 0; e < 4; e++) sc[i][e] = 0.f;

#pragma unroll
        for (int t = 0; t < 4; t++) {
            uint32_t kbh[4][4], kbl[4][4];
#pragma unroll
            for (int g16 = 0; g16 < 4; g16++) {
                const uint32_t off = (uint32_t)((16 * g16 + b_n) * ASTB + (t * 16 + b_k) * 2);
                ldsm4(kbh[g16], st + off);
                ldsm4(kbl[g16], st + KV_ARR + off);
            }
#pragma unroll
            for (int nf = 0; nf < 8; nf++) {
                const int g16 = nf >> 1;
                const int sel = (nf & 1) * 2;
                mma16816(sc[nf], qa_h[t], kbh[g16][sel], kbh[g16][sel + 1]);
                mma16816(sc[nf], qa_h[t], kbl[g16][sel], kbl[g16][sel + 1]);
                mma16816(sc[nf], qa_l[t], kbh[g16][sel], kbh[g16][sel + 1]);
            }
        }

        // ---- scale + causal mask + online softmax ----
#pragma unroll
        for (int nf = 0; nf < 8; nf++)
#pragma unroll
            for (int e = 0; e < 4; e++) sc[nf][e] *= 0.125f;

        if (kt == qt) {
            const int lr0 = 16 * w + g;
            const int lr1 = lr0 + 8;
#pragma unroll
            for (int nf = 0; nf < 8; nf++) {
                const int c0 = 8 * nf + 2 * q;
                if (c0     > lr0) sc[nf][0] = -INFINITY;
                if (c0 + 1 > lr0) sc[nf][1] = -INFINITY;
                if (c0     > lr1) sc[nf][2] = -INFINITY;
                if (c0 + 1 > lr1) sc[nf][3] = -INFINITY;
            }
        }

        float mx0 = -INFINITY, mx1 = -INFINITY;
#pragma unroll
        for (int nf = 0; nf < 8; nf++) {
            mx0 = fmaxf(mx0, fmaxf(sc[nf][0], sc[nf][1]));
            mx1 = fmaxf(mx1, fmaxf(sc[nf][2], sc[nf][3]));
        }
        mx0 = fmaxf(mx0, __shfl_xor_sync(0xffffffffu, mx0, 1));
        mx0 = fmaxf(mx0, __shfl_xor_sync(0xffffffffu, mx0, 2));
        mx1 = fmaxf(mx1, __shfl_xor_sync(0xffffffffu, mx1, 1));
        mx1 = fmaxf(mx1, __shfl_xor_sync(0xffffffffu, mx1, 2));

        const float mn0 = fmaxf(m0, mx0), mn1 = fmaxf(m1, mx1);
        const float al0 = __expf(m0 - mn0), al1 = __expf(m1 - mn1);

        float ps0 = 0.f, ps1 = 0.f;
#pragma unroll
        for (int nf = 0; nf < 8; nf++) {
            sc[nf][0] = __expf(sc[nf][0] - mn0);
            sc[nf][1] = __expf(sc[nf][1] - mn0);
            sc[nf][2] = __expf(sc[nf][2] - mn1);
            sc[nf][3] = __expf(sc[nf][3] - mn1);
            ps0 += sc[nf][0] + sc[nf][1];
            ps1 += sc[nf][2] + sc[nf][3];
        }
        ps0 += __shfl_xor_sync(0xffffffffu, ps0, 1);
        ps0 += __shfl_xor_sync(0xffffffffu, ps0, 2);
        ps1 += __shfl_xor_sync(0xffffffffu, ps1, 1);
        ps1 += __shfl_xor_sync(0xffffffffu, ps1, 2);

        l0 = l0 * al0 + ps0;
        l1 = l1 * al1 + ps1;
        m0 = mn0; m1 = mn1;
#pragma unroll
        for (int df = 0; df < 8; df++) {
            acc_o[df][0] *= al0; acc_o[df][1] *= al0;
            acc_o[df][2] *= al1; acc_o[df][3] *= al1;
        }

        // ---- pack P into split A-fragments ----
        uint32_t pa_h[4][4], pa_l[4][4];
#pragma unroll
        for (int t = 0; t < 4; t++) {
            split2(sc[2 * t][0],     sc[2 * t][1],     pa_h[t][0], pa_l[t][0]);
            split2(sc[2 * t][2],     sc[2 * t][3],     pa_h[t][1], pa_l[t][1]);
            split2(sc[2 * t + 1][0], sc[2 * t + 1][1], pa_h[t][2], pa_l[t][2]);
            split2(sc[2 * t + 1][2], sc[2 * t + 1][3], pa_h[t][3], pa_l[t][3]);
        }

        // ---- O += P V (3-term split), V via ldmatrix.trans ----
#pragma unroll
        for (int t = 0; t < 4; t++) {
            uint32_t vbh[4][4], vbl[4][4];
#pragma unroll
            for (int g16 = 0; g16 < 4; g16++) {
                const uint32_t off =
                    (uint32_t)((16 * t + v_kv) * ASTB + (16 * g16 + v_d) * 2);
                ldsm4t(vbh[g16], st + 2 * KV_ARR + off);
                ldsm4t(vbl[g16], st + 3 * KV_ARR + off);
            }
#pragma unroll
            for (int df = 0; df < 8; df++) {
                const int g16 = df >> 1;
                const int sel = (df & 1) * 2;
                mma16816(acc_o[df], pa_h[t], vbh[g16][sel], vbh[g16][sel + 1]);
                mma16816(acc_o[df], pa_h[t], vbl[g16][sel], vbl[g16][sel + 1]);
                mma16816(acc_o[df], pa_l[t], vbh[g16][sel], vbh[g16][sel + 1]);
            }
        }
        __syncthreads();
    }

    // ---- epilogue: normalize, split to bf16 hi/lo, write [B,S,D] ----
    const float i0 = 1.f / l0, i1 = 1.f / l1;
    const int s0 = qt * 64 + 16 * w + g;
    const size_t base0 = ((size_t)(b * Sq + s0)) * Dm + h * DHe;
    const size_t base1 = base0 + (size_t)8 * Dm;
#pragma unroll
    for (int df = 0; df < 8; df++) {
        const int d = 8 * df + 2 * q;
        uint32_t hp, lp;
        split2(acc_o[df][0] * i0, acc_o[df][1] * i0, hp, lp);
        *(uint32_t*)(Ch + base0 + d) = hp;
        *(uint32_t*)(Cl + base0 + d) = lp;
        split2(acc_o[df][2] * i1, acc_o[df][3] * i1, hp, lp);
        *(uint32_t*)(Ch + base1 + d) = hp;
        *(uint32_t*)(Cl + base1 + d) = lp;
    }
}

// ---------------------------------------------------------------------------
extern "C" void kernel_launch(void* const* d_in, const int* in_sizes, int n_in,
                              void* d_out, int out_size)
{
    const float* x  = (const float*)d_in[0];
    const float* Wq = (const float*)d_in[1];
    const float* Wk = (const float*)d_in[2];
    const float* Wv = (const float*)d_in[3];
    const float* Wo = (const float*)d_in[4];
    float* out = (float*)d_out;

    bf16 *xh, *xl, *wh, *wl, *qh, *ql, *kh, *kl, *vh, *vl, *ch, *cl;
    cudaGetSymbolAddress((void**)&xh, g_xh);
    cudaGetSymbolAddress((void**)&xl, g_xl);
    cudaGetSymbolAddress((void**)&wh, g_wh);
    cudaGetSymbolAddress((void**)&wl, g_wl);
    cudaGetSymbolAddress((void**)&qh, g_qh);
    cudaGetSymbolAddress((void**)&ql, g_ql);
    cudaGetSymbolAddress((void**)&kh, g_kh);
    cudaGetSymbolAddress((void**)&kl, g_kl);
    cudaGetSymbolAddress((void**)&vh, g_vh);
    cudaGetSymbolAddress((void**)&vl, g_vl);
    cudaGetSymbolAddress((void**)&ch, g_ch);
    cudaGetSymbolAddress((void**)&cl, g_cl);

    cudaFuncSetAttribute(gemm_hmma<true>,  cudaFuncAttributeMaxDynamicSharedMemorySize, SMEM_GEMM);
    cudaFuncSetAttribute(gemm_hmma<false>, cudaFuncAttributeMaxDynamicSharedMemorySize, SMEM_GEMM);
    cudaFuncSetAttribute(attn_tc, cudaFuncAttributeMaxDynamicSharedMemorySize, SMEM_ATT);

    const int n4 = Mrows * Dm / 4;
    const size_t WSZ = (size_t)Dm * Dm;

    fsplit_kernel<<<2048, 256>>>(x, xh, xl, n4);
    {
        dim3 wg(Dm / 32, Dm / 32);
        wsplit_kernel<<<wg, 256>>>(Wq, wh + 0 * WSZ, wl + 0 * WSZ);
        wsplit_kernel<<<wg, 256>>>(Wk, wh + 1 * WSZ, wl + 1 * WSZ);
        wsplit_kernel<<<wg, 256>>>(Wv, wh + 2 * WSZ, wl + 2 * WSZ);
        wsplit_kernel<<<wg, 256>>>(Wo, wh + 3 * WSZ, wl + 3 * WSZ);
    }

    const dim3 gg(Dm / 128, Mrows / 128);   // (8, 64)
    gemm_hmma<true><<<gg, 256, SMEM_GEMM>>>(xh, xl, wh + 0 * WSZ, wl + 0 * WSZ, nullptr, qh, ql);
    gemm_hmma<true><<<gg, 256, SMEM_GEMM>>>(xh, xl, wh + 1 * WSZ, wl + 1 * WSZ, nullptr, kh, kl);
    gemm_hmma<true><<<gg, 256, SMEM_GEMM>>>(xh, xl, wh + 2 * WSZ, wl + 2 * WSZ, nullptr, vh, vl);

    attn_tc<<<dim3(Sq / 64, Bq * Hn), 128, SMEM_ATT>>>(qh, ql, kh, kl, vh, vl, ch, cl);

    gemm_hmma<false><<<gg, 256, SMEM_GEMM>>>(ch, cl, wh + 3 * WSZ, wl + 3 * WSZ, out, nullptr, nullptr);
}